// round 1
// baseline (speedup 1.0000x reference)
#include <cuda_runtime.h>
#include <math.h>

#define BATCH 2
#define SEQ   2048
#define CH    2048
#define NH    16
#define HD    128
#define WIN   512
#define MROWS (BATCH*SEQ)   // 4096

// ---------------- scratch (static device globals; no allocation allowed) ----
__device__ float g_Q[MROWS*CH];
__device__ float g_K[MROWS*CH];
__device__ float g_V[MROWS*CH];
__device__ float g_A[MROWS*CH];

// ---------------- f32x2 packed helpers ------------------------------------
__device__ __forceinline__ unsigned long long pack2(float lo, float hi) {
    unsigned long long r;
    asm("mov.b64 %0, {%1, %2};" : "=l"(r) : "f"(lo), "f"(hi));
    return r;
}
__device__ __forceinline__ float2 unpack2(unsigned long long v) {
    float2 f;
    asm("mov.b64 {%0, %1}, %2;" : "=f"(f.x), "=f"(f.y) : "l"(v));
    return f;
}
__device__ __forceinline__ unsigned long long ffma2(unsigned long long a,
                                                    unsigned long long b,
                                                    unsigned long long c) {
    unsigned long long d;
    asm("fma.rn.f32x2 %0, %1, %2, %3;" : "=l"(d) : "l"(a), "l"(b), "l"(c));
    return d;
}
__device__ __forceinline__ unsigned long long fmul2(unsigned long long a,
                                                    unsigned long long b) {
    unsigned long long d;
    asm("mul.rn.f32x2 %0, %1, %2;" : "=l"(d) : "l"(a), "l"(b));
    return d;
}

// ---------------- GEMM: C[4096,2048] = A[4096,2048] * W[2048,2048] ---------
// 128x128 block, BK=8, 256 threads, 8x8 per thread, f32x2 packed FMA.
#define GK 2048
#define GN 2048

__global__ __launch_bounds__(256) void gemm128(const float* __restrict__ A,
                                               const float* __restrict__ W,
                                               float* __restrict__ Cout) {
    __shared__ float As[8][128];
    __shared__ float Bs[8][128];

    const int tid = threadIdx.x;
    const int tx = tid & 15;          // 0..15 (N groups of 8)
    const int ty = tid >> 4;          // 0..15 (M groups of 8)
    const int row0 = blockIdx.y * 128;
    const int col0 = blockIdx.x * 128;

    // A tile loader: 128 rows x 8 k, float4 along k (2 per row)
    const int arow = tid >> 1;
    const int acol = (tid & 1) * 4;
    // B tile loader: 8 rows x 128 cols, float4 along n
    const int brow = tid >> 5;
    const int bcol = (tid & 31) * 4;

    const float* Aptr = A + (size_t)(row0 + arow) * GK + acol;
    const float* Wptr = W + (size_t)brow * GN + col0 + bcol;

    unsigned long long cc[8][4] = {};

    for (int kt = 0; kt < GK; kt += 8) {
        float4 av = *(const float4*)Aptr;  Aptr += 8;
        float4 bv = *(const float4*)Wptr;  Wptr += (size_t)8 * GN;

        As[acol + 0][arow] = av.x;
        As[acol + 1][arow] = av.y;
        As[acol + 2][arow] = av.z;
        As[acol + 3][arow] = av.w;
        *(float4*)&Bs[brow][bcol] = bv;
        __syncthreads();

        #pragma unroll
        for (int k = 0; k < 8; k++) {
            float a[8];
            unsigned long long bp[4];
            #pragma unroll
            for (int i = 0; i < 8; i++) a[i] = As[k][ty * 8 + i];
            #pragma unroll
            for (int j = 0; j < 4; j++)
                bp[j] = *(const unsigned long long*)&Bs[k][tx * 8 + 2 * j];
            #pragma unroll
            for (int i = 0; i < 8; i++) {
                unsigned long long ap = pack2(a[i], a[i]);
                #pragma unroll
                for (int j = 0; j < 4; j++)
                    cc[i][j] = ffma2(ap, bp[j], cc[i][j]);
            }
        }
        __syncthreads();
    }

    #pragma unroll
    for (int i = 0; i < 8; i++) {
        size_t rbase = (size_t)(row0 + ty * 8 + i) * GN + col0 + tx * 8;
        #pragma unroll
        for (int j = 0; j < 4; j++) {
            float2 v = unpack2(cc[i][j]);
            *(float2*)&Cout[rbase + 2 * j] = v;
        }
    }
}

// ---------------- RoPE: in-place on Q and K --------------------------------
__global__ __launch_bounds__(256) void rope_kernel(float* __restrict__ Q,
                                                   float* __restrict__ K) {
    int idx = blockIdx.x * blockDim.x + threadIdx.x;
    // total = B*T*H*(D/2) = 2^22
    if (idx >= BATCH * SEQ * NH * (HD / 2)) return;
    int d = idx & 63;
    int h = (idx >> 6) & (NH - 1);
    int t = (idx >> 10) & (SEQ - 1);
    int b = idx >> 21;

    double inv = exp(-((double)d / 64.0) * log(10000.0));
    double ang = (double)t * inv;
    double sd, cd;
    sincos(ang, &sd, &cd);
    float c = (float)cd, s = (float)sd;

    size_t base = ((size_t)(b * SEQ + t)) * CH + h * HD + d;
    float q1 = Q[base], q2 = Q[base + 64];
    Q[base]      = q1 * c - q2 * s;
    Q[base + 64] = q1 * s + q2 * c;
    float k1 = K[base], k2 = K[base + 64];
    K[base]      = k1 * c - k2 * s;
    K[base + 64] = k1 * s + k2 * c;
}

// ---------------- Attention (flash-style, inverted-window mask) ------------
// grid: (SEQ/64, BATCH*NH), block 256.  Dynamic smem:
//   Qs 64x128 | Ks 64x128 | Vs 64x128 | Ps 64x64  = 114688 bytes
__global__ __launch_bounds__(256) void attn_kernel() {
    extern __shared__ float sm[];
    float* Qs = sm;
    float* Ks = sm + 8192;
    float* Vs = sm + 16384;
    float* Ps = sm + 24576;

    const int bh = blockIdx.y;
    const int b = bh >> 4;
    const int h = bh & 15;
    const int qbase = blockIdx.x * 64;
    const int tid = threadIdx.x;
    const int tx = tid & 15;
    const int ty = tid >> 4;
    const float scale = 0.08838834764831845f;  // 1/sqrt(128)

    const float* Qg = g_Q + (size_t)(b * SEQ) * CH + h * HD;
    const float* Kg = g_K + (size_t)(b * SEQ) * CH + h * HD;
    const float* Vg = g_V + (size_t)(b * SEQ) * CH + h * HD;

    // load Q tile
    for (int idx = tid; idx < 64 * 32; idx += 256) {
        int r = idx >> 5, c4 = (idx & 31) << 2;
        *(float4*)&Qs[r * 128 + c4] =
            *(const float4*)&Qg[(size_t)(qbase + r) * CH + c4];
    }

    float mrow[4], lrow[4];
    unsigned long long acc[4][4];
    #pragma unroll
    for (int i = 0; i < 4; i++) {
        mrow[i] = -1e30f;
        lrow[i] = 0.0f;
        #pragma unroll
        for (int j = 0; j < 4; j++) acc[i][j] = 0ull;
    }
    __syncthreads();

    for (int kb = 0; kb < SEQ; kb += 64) {
        // tile fully inside the masked band? skip.
        bool skip = (kb + 63 <= qbase) && (kb >= qbase + 63 - (WIN - 1));
        if (skip) continue;

        for (int idx = tid; idx < 64 * 32; idx += 256) {
            int r = idx >> 5, c4 = (idx & 31) << 2;
            *(float4*)&Ks[r * 128 + c4] =
                *(const float4*)&Kg[(size_t)(kb + r) * CH + c4];
            *(float4*)&Vs[r * 128 + c4] =
                *(const float4*)&Vg[(size_t)(kb + r) * CH + c4];
        }
        __syncthreads();

        // S = Q K^T (4x4 per thread)
        float s[4][4] = {};
        #pragma unroll 8
        for (int d4 = 0; d4 < 128; d4 += 4) {
            float4 q[4], k[4];
            #pragma unroll
            for (int ii = 0; ii < 4; ii++)
                q[ii] = *(const float4*)&Qs[(ty * 4 + ii) * 128 + d4];
            #pragma unroll
            for (int jj = 0; jj < 4; jj++)
                k[jj] = *(const float4*)&Ks[(tx * 4 + jj) * 128 + d4];
            #pragma unroll
            for (int ii = 0; ii < 4; ii++)
                #pragma unroll
                for (int jj = 0; jj < 4; jj++) {
                    s[ii][jj] += q[ii].x * k[jj].x;
                    s[ii][jj] += q[ii].y * k[jj].y;
                    s[ii][jj] += q[ii].z * k[jj].z;
                    s[ii][jj] += q[ii].w * k[jj].w;
                }
        }

        // scale + inverted-window mask
        #pragma unroll
        for (int ii = 0; ii < 4; ii++) {
            int i = qbase + ty * 4 + ii;
            #pragma unroll
            for (int jj = 0; jj < 4; jj++) {
                int j = kb + tx * 4 + jj;
                float v = s[ii][jj] * scale;
                bool masked = (j <= i) && (j >= i - (WIN - 1));
                s[ii][jj] = masked ? -1e30f : v;
            }
        }

        // online softmax update per row
        #pragma unroll
        for (int ii = 0; ii < 4; ii++) {
            float rmax = fmaxf(fmaxf(s[ii][0], s[ii][1]),
                               fmaxf(s[ii][2], s[ii][3]));
            #pragma unroll
            for (int m = 1; m < 16; m <<= 1)
                rmax = fmaxf(rmax, __shfl_xor_sync(0xffffffffu, rmax, m));
            float mnew = fmaxf(mrow[ii], rmax);
            float corr = __expf(mrow[ii] - mnew);
            float psum = 0.0f;
            #pragma unroll
            for (int jj = 0; jj < 4; jj++) {
                float p = __expf(s[ii][jj] - mnew);
                s[ii][jj] = p;
                psum += p;
            }
            #pragma unroll
            for (int m = 1; m < 16; m <<= 1)
                psum += __shfl_xor_sync(0xffffffffu, psum, m);
            lrow[ii] = lrow[ii] * corr + psum;
            mrow[ii] = mnew;
            unsigned long long cp = pack2(corr, corr);
            #pragma unroll
            for (int j2 = 0; j2 < 4; j2++)
                acc[ii][j2] = fmul2(acc[ii][j2], cp);
            #pragma unroll
            for (int jj = 0; jj < 4; jj++)
                Ps[(ty * 4 + ii) * 64 + tx * 4 + jj] = s[ii][jj];
        }
        __syncthreads();

        // O += P * V  (cols tx*8 .. tx*8+7, packed pairs)
        #pragma unroll 8
        for (int kk = 0; kk < 64; kk++) {
            float p[4];
            #pragma unroll
            for (int ii = 0; ii < 4; ii++)
                p[ii] = Ps[(ty * 4 + ii) * 64 + kk];
            unsigned long long vp[4];
            #pragma unroll
            for (int j2 = 0; j2 < 4; j2++)
                vp[j2] = *(const unsigned long long*)&Vs[kk * 128 + tx * 8 + 2 * j2];
            #pragma unroll
            for (int ii = 0; ii < 4; ii++) {
                unsigned long long pp = pack2(p[ii], p[ii]);
                #pragma unroll
                for (int j2 = 0; j2 < 4; j2++)
                    acc[ii][j2] = ffma2(pp, vp[j2], acc[ii][j2]);
            }
        }
        __syncthreads();
    }

    // epilogue: normalize and store
    float* Og = g_A + (size_t)(b * SEQ) * CH + h * HD;
    #pragma unroll
    for (int ii = 0; ii < 4; ii++) {
        float inv_l = 1.0f / lrow[ii];
        size_t rbase = (size_t)(qbase + ty * 4 + ii) * CH + tx * 8;
        #pragma unroll
        for (int j2 = 0; j2 < 4; j2++) {
            float2 v = unpack2(acc[ii][j2]);
            v.x *= inv_l;
            v.y *= inv_l;
            *(float2*)&Og[rbase + 2 * j2] = v;
        }
    }
}

// ---------------- launch ----------------------------------------------------
extern "C" void kernel_launch(void* const* d_in, const int* in_sizes, int n_in,
                              void* d_out, int out_size) {
    const float* x  = (const float*)d_in[0];
    const float* Wq = (const float*)d_in[1];
    const float* Wk = (const float*)d_in[2];
    const float* Wv = (const float*)d_in[3];
    const float* Wo = (const float*)d_in[4];
    float* out = (float*)d_out;

    float *Qp, *Kp, *Vp, *Ap;
    cudaGetSymbolAddress((void**)&Qp, g_Q);
    cudaGetSymbolAddress((void**)&Kp, g_K);
    cudaGetSymbolAddress((void**)&Vp, g_V);
    cudaGetSymbolAddress((void**)&Ap, g_A);

    dim3 gg(GN / 128, MROWS / 128);  // (16, 32)
    gemm128<<<gg, 256>>>(x, Wq, Qp);
    gemm128<<<gg, 256>>>(x, Wk, Kp);
    gemm128<<<gg, 256>>>(x, Wv, Vp);

    rope_kernel<<<(BATCH * SEQ * NH * (HD / 2)) / 256, 256>>>(Qp, Kp);

    static bool attr_set = false;
    if (!attr_set) {
        cudaFuncSetAttribute(attn_kernel,
                             cudaFuncAttributeMaxDynamicSharedMemorySize,
                             114688);
        attr_set = true;
    }
    attn_kernel<<<dim3(SEQ / 64, BATCH * NH), 256, 114688>>>();

    gemm128<<<gg, 256>>>(Ap, Wo, out);
}

// round 3
// speedup vs baseline: 1.4336x; 1.4336x over previous
#include <cuda_runtime.h>
#include <math.h>
#include <stdint.h>

#define BATCH 2
#define SEQ   2048
#define CH    2048
#define NH    16
#define HD    128
#define WIN   512
#define MROWS (BATCH*SEQ)   // 4096

// ---------------- scratch (static device globals) ---------------------------
__device__ float g_Q[MROWS*CH];
__device__ float g_K[MROWS*CH];
__device__ float g_V[MROWS*CH];
__device__ float g_A[MROWS*CH];
__device__ float g_cos[SEQ*64];
__device__ float g_sin[SEQ*64];

// ---------------- helpers ---------------------------------------------------
__device__ __forceinline__ unsigned long long pack2(float lo, float hi) {
    unsigned long long r;
    asm("mov.b64 %0, {%1, %2};" : "=l"(r) : "f"(lo), "f"(hi));
    return r;
}
__device__ __forceinline__ float2 unpack2(unsigned long long v) {
    float2 f;
    asm("mov.b64 {%0, %1}, %2;" : "=f"(f.x), "=f"(f.y) : "l"(v));
    return f;
}
__device__ __forceinline__ unsigned long long ffma2(unsigned long long a,
                                                    unsigned long long b,
                                                    unsigned long long c) {
    unsigned long long d;
    asm("fma.rn.f32x2 %0, %1, %2, %3;" : "=l"(d) : "l"(a), "l"(b), "l"(c));
    return d;
}
__device__ __forceinline__ unsigned long long fmul2(unsigned long long a,
                                                    unsigned long long b) {
    unsigned long long d;
    asm("mul.rn.f32x2 %0, %1, %2;" : "=l"(d) : "l"(a), "l"(b));
    return d;
}
__device__ __forceinline__ float tf32r(float x) {
    uint32_t u;
    asm("cvt.rna.tf32.f32 %0, %1;" : "=r"(u) : "f"(x));
    return __uint_as_float(u);
}
__device__ __forceinline__ void mma8(float* d, const float* a, const float* b) {
    asm volatile(
        "mma.sync.aligned.m16n8k8.row.col.f32.tf32.tf32.f32 "
        "{%0,%1,%2,%3}, {%4,%5,%6,%7}, {%8,%9}, {%0,%1,%2,%3};"
        : "+f"(d[0]), "+f"(d[1]), "+f"(d[2]), "+f"(d[3])
        : "r"(__float_as_uint(a[0])), "r"(__float_as_uint(a[1])),
          "r"(__float_as_uint(a[2])), "r"(__float_as_uint(a[3])),
          "r"(__float_as_uint(b[0])), "r"(__float_as_uint(b[1])));
}

// ---------------- tf32 tensor-core GEMM -------------------------------------
// C[4096,2048] = A[4096,2048] x W[2048,2048]
// block 128x128, BK=32, 256 threads (8 warps, 2x4 warp grid, warp tile 64x32)
// smem: k-major tiles, stride 136 floats (even -> float4-aligned rows,
// 136 mod 32 = 8 -> fragment reads hit all 32 banks). Double-buffered.
#define GK 2048
#define GN 2048
#define SA 136
#define TILE_F (32*SA)           // 4352 floats per A or B tile
#define BUF_F  (2*TILE_F)        // 8704 floats per buffer
#define GEMM_SMEM (2*BUF_F*4)    // 69632 bytes

__global__ __launch_bounds__(256, 1) void gemm_tf32(const float* __restrict__ A,
                                                    const float* __restrict__ W,
                                                    float* __restrict__ C) {
    extern __shared__ float sm[];
    const int tid  = threadIdx.x;
    const int lane = tid & 31;
    const int wid  = tid >> 5;
    const int wm   = (wid >> 2) * 64;   // warp m offset
    const int wn   = (wid & 3) * 32;    // warp n offset
    const int lm   = lane >> 2;         // 0..7
    const int lk   = lane & 3;          // 0..3
    const int row0 = blockIdx.y * 128;
    const int col0 = blockIdx.x * 128;

    // loader mapping
    const int am = tid >> 3;            // 0..31 (A row within 32-row slab)
    const int ak = (tid & 7) << 2;      // 0..28 (A k within tile, float4)
    const int bk = tid >> 5;            // 0..7  (B k within 8-row slab)
    const int bn = (tid & 31) << 2;     // 0..124 (B n, float4)

    float acc[4][4][4];
    #pragma unroll
    for (int i = 0; i < 4; i++)
        #pragma unroll
        for (int j = 0; j < 4; j++)
            #pragma unroll
            for (int r = 0; r < 4; r++) acc[i][j][r] = 0.0f;

    float4 aR[4], bR[4];

    auto loadG = [&](int kt) {
        #pragma unroll
        for (int i = 0; i < 4; i++) {
            aR[i] = *(const float4*)&A[(size_t)(row0 + i * 32 + am) * GK + kt + ak];
            bR[i] = *(const float4*)&W[(size_t)(kt + i * 8 + bk) * GN + col0 + bn];
        }
    };
    auto storeS = [&](int buf) {
        float* As = sm + buf * BUF_F;
        float* Bs = As + TILE_F;
        #pragma unroll
        for (int i = 0; i < 4; i++) {
            As[(ak + 0) * SA + i * 32 + am] = tf32r(aR[i].x);
            As[(ak + 1) * SA + i * 32 + am] = tf32r(aR[i].y);
            As[(ak + 2) * SA + i * 32 + am] = tf32r(aR[i].z);
            As[(ak + 3) * SA + i * 32 + am] = tf32r(aR[i].w);
            float4 bv;
            bv.x = tf32r(bR[i].x); bv.y = tf32r(bR[i].y);
            bv.z = tf32r(bR[i].z); bv.w = tf32r(bR[i].w);
            *(float4*)&Bs[(i * 8 + bk) * SA + bn] = bv;
        }
    };
    auto compute = [&](int buf) {
        const float* As = sm + buf * BUF_F;
        const float* Bs = As + TILE_F;
        #pragma unroll
        for (int ks = 0; ks < 4; ks++) {
            const int k0 = ks * 8;
            const float* Ap = As + (k0 + lk) * SA;
            const float* Bp = Bs + (k0 + lk) * SA;
            float af[4][4], bf[4][2];
            #pragma unroll
            for (int i = 0; i < 4; i++) {
                int m0 = wm + i * 16 + lm;
                af[i][0] = Ap[m0];
                af[i][1] = Ap[m0 + 8];
                af[i][2] = Ap[4 * SA + m0];
                af[i][3] = Ap[4 * SA + m0 + 8];
            }
            #pragma unroll
            for (int j = 0; j < 4; j++) {
                int n0 = wn + j * 8 + lm;
                bf[j][0] = Bp[n0];
                bf[j][1] = Bp[4 * SA + n0];
            }
            #pragma unroll
            for (int i = 0; i < 4; i++)
                #pragma unroll
                for (int j = 0; j < 4; j++)
                    mma8(acc[i][j], af[i], bf[j]);
        }
    };

    loadG(0);
    storeS(0);
    __syncthreads();

    #pragma unroll 1
    for (int kt = 0; kt < GK; kt += 32) {
        const int buf = (kt >> 5) & 1;
        const bool hasNext = (kt + 32) < GK;
        if (hasNext) loadG(kt + 32);
        compute(buf);
        if (hasNext) storeS(buf ^ 1);
        __syncthreads();
    }

    // epilogue
    #pragma unroll
    for (int i = 0; i < 4; i++) {
        #pragma unroll
        for (int j = 0; j < 4; j++) {
            int r = row0 + wm + i * 16 + lm;
            int c = col0 + wn + j * 8 + 2 * lk;
            *(float2*)&C[(size_t)r * GN + c] =
                make_float2(acc[i][j][0], acc[i][j][1]);
            *(float2*)&C[(size_t)(r + 8) * GN + c] =
                make_float2(acc[i][j][2], acc[i][j][3]);
        }
    }
}

// ---------------- RoPE: table build (fp64, tiny) + apply (fp32, bw-bound) ---
__global__ __launch_bounds__(256) void rope_tab_kernel() {
    int idx = blockIdx.x * blockDim.x + threadIdx.x;
    if (idx >= SEQ * 64) return;
    int d = idx & 63;
    int t = idx >> 6;
    double inv = exp(-((double)d / 64.0) * log(10000.0));
    double sd, cd;
    sincos((double)t * inv, &sd, &cd);
    g_cos[idx] = (float)cd;
    g_sin[idx] = (float)sd;
}

__global__ __launch_bounds__(256) void rope_apply_kernel(float* __restrict__ Q,
                                                         float* __restrict__ K) {
    int idx = blockIdx.x * blockDim.x + threadIdx.x;
    if (idx >= BATCH * SEQ * NH * 64) return;
    int d = idx & 63;
    int h = (idx >> 6) & (NH - 1);
    int t = (idx >> 10) & (SEQ - 1);
    int b = idx >> 21;

    float c = g_cos[(t << 6) + d];
    float s = g_sin[(t << 6) + d];

    size_t base = ((size_t)(b * SEQ + t)) * CH + h * HD + d;
    float q1 = Q[base], q2 = Q[base + 64];
    Q[base]      = q1 * c - q2 * s;
    Q[base + 64] = q1 * s + q2 * c;
    float k1 = K[base], k2 = K[base + 64];
    K[base]      = k1 * c - k2 * s;
    K[base + 64] = k1 * s + k2 * c;
}

// ---------------- Attention (flash-style, inverted-window mask) ------------
__global__ __launch_bounds__(256) void attn_kernel() {
    extern __shared__ float smA[];
    float* Qs = smA;
    float* Ks = smA + 8192;
    float* Vs = smA + 16384;
    float* Ps = smA + 24576;

    const int bh = blockIdx.y;
    const int b = bh >> 4;
    const int h = bh & 15;
    const int qbase = blockIdx.x * 64;
    const int tid = threadIdx.x;
    const int tx = tid & 15;
    const int ty = tid >> 4;
    const float scale = 0.08838834764831845f;  // 1/sqrt(128)

    const float* Qg = g_Q + (size_t)(b * SEQ) * CH + h * HD;
    const float* Kg = g_K + (size_t)(b * SEQ) * CH + h * HD;
    const float* Vg = g_V + (size_t)(b * SEQ) * CH + h * HD;

    for (int idx = tid; idx < 64 * 32; idx += 256) {
        int r = idx >> 5, c4 = (idx & 31) << 2;
        *(float4*)&Qs[r * 128 + c4] =
            *(const float4*)&Qg[(size_t)(qbase + r) * CH + c4];
    }

    float mrow[4], lrow[4];
    unsigned long long acc[4][4];
    #pragma unroll
    for (int i = 0; i < 4; i++) {
        mrow[i] = -1e30f;
        lrow[i] = 0.0f;
        #pragma unroll
        for (int j = 0; j < 4; j++) acc[i][j] = 0ull;
    }
    __syncthreads();

    for (int kb = 0; kb < SEQ; kb += 64) {
        bool skip = (kb + 63 <= qbase) && (kb >= qbase + 63 - (WIN - 1));
        if (skip) continue;

        for (int idx = tid; idx < 64 * 32; idx += 256) {
            int r = idx >> 5, c4 = (idx & 31) << 2;
            *(float4*)&Ks[r * 128 + c4] =
                *(const float4*)&Kg[(size_t)(kb + r) * CH + c4];
            *(float4*)&Vs[r * 128 + c4] =
                *(const float4*)&Vg[(size_t)(kb + r) * CH + c4];
        }
        __syncthreads();

        float s[4][4] = {};
        #pragma unroll 8
        for (int d4 = 0; d4 < 128; d4 += 4) {
            float4 q[4], k[4];
            #pragma unroll
            for (int ii = 0; ii < 4; ii++)
                q[ii] = *(const float4*)&Qs[(ty * 4 + ii) * 128 + d4];
            #pragma unroll
            for (int jj = 0; jj < 4; jj++)
                k[jj] = *(const float4*)&Ks[(tx * 4 + jj) * 128 + d4];
            #pragma unroll
            for (int ii = 0; ii < 4; ii++)
                #pragma unroll
                for (int jj = 0; jj < 4; jj++) {
                    s[ii][jj] += q[ii].x * k[jj].x;
                    s[ii][jj] += q[ii].y * k[jj].y;
                    s[ii][jj] += q[ii].z * k[jj].z;
                    s[ii][jj] += q[ii].w * k[jj].w;
                }
        }

        #pragma unroll
        for (int ii = 0; ii < 4; ii++) {
            int i = qbase + ty * 4 + ii;
            #pragma unroll
            for (int jj = 0; jj < 4; jj++) {
                int j = kb + tx * 4 + jj;
                float v = s[ii][jj] * scale;
                bool masked = (j <= i) && (j >= i - (WIN - 1));
                s[ii][jj] = masked ? -1e30f : v;
            }
        }

        #pragma unroll
        for (int ii = 0; ii < 4; ii++) {
            float rmax = fmaxf(fmaxf(s[ii][0], s[ii][1]),
                               fmaxf(s[ii][2], s[ii][3]));
            #pragma unroll
            for (int m = 1; m < 16; m <<= 1)
                rmax = fmaxf(rmax, __shfl_xor_sync(0xffffffffu, rmax, m));
            float mnew = fmaxf(mrow[ii], rmax);
            float corr = __expf(mrow[ii] - mnew);
            float psum = 0.0f;
            #pragma unroll
            for (int jj = 0; jj < 4; jj++) {
                float p = __expf(s[ii][jj] - mnew);
                s[ii][jj] = p;
                psum += p;
            }
            #pragma unroll
            for (int m = 1; m < 16; m <<= 1)
                psum += __shfl_xor_sync(0xffffffffu, psum, m);
            lrow[ii] = lrow[ii] * corr + psum;
            mrow[ii] = mnew;
            unsigned long long cp = pack2(corr, corr);
            #pragma unroll
            for (int j2 = 0; j2 < 4; j2++)
                acc[ii][j2] = fmul2(acc[ii][j2], cp);
            #pragma unroll
            for (int jj = 0; jj < 4; jj++)
                Ps[(ty * 4 + ii) * 64 + tx * 4 + jj] = s[ii][jj];
        }
        __syncthreads();

        #pragma unroll 8
        for (int kk = 0; kk < 64; kk++) {
            float p[4];
            #pragma unroll
            for (int ii = 0; ii < 4; ii++)
                p[ii] = Ps[(ty * 4 + ii) * 64 + kk];
            unsigned long long vp[4];
            #pragma unroll
            for (int j2 = 0; j2 < 4; j2++)
                vp[j2] = *(const unsigned long long*)&Vs[kk * 128 + tx * 8 + 2 * j2];
            #pragma unroll
            for (int ii = 0; ii < 4; ii++) {
                unsigned long long pp = pack2(p[ii], p[ii]);
                #pragma unroll
                for (int j2 = 0; j2 < 4; j2++)
                    acc[ii][j2] = ffma2(pp, vp[j2], acc[ii][j2]);
            }
        }
        __syncthreads();
    }

    float* Og = g_A + (size_t)(b * SEQ) * CH + h * HD;
    #pragma unroll
    for (int ii = 0; ii < 4; ii++) {
        float inv_l = 1.0f / lrow[ii];
        size_t rbase = (size_t)(qbase + ty * 4 + ii) * CH + tx * 8;
        #pragma unroll
        for (int j2 = 0; j2 < 4; j2++) {
            float2 v = unpack2(acc[ii][j2]);
            v.x *= inv_l;
            v.y *= inv_l;
            *(float2*)&Og[rbase + 2 * j2] = v;
        }
    }
}

// ---------------- launch ----------------------------------------------------
extern "C" void kernel_launch(void* const* d_in, const int* in_sizes, int n_in,
                              void* d_out, int out_size) {
    const float* x  = (const float*)d_in[0];
    const float* Wq = (const float*)d_in[1];
    const float* Wk = (const float*)d_in[2];
    const float* Wv = (const float*)d_in[3];
    const float* Wo = (const float*)d_in[4];
    float* out = (float*)d_out;

    float *Qp, *Kp, *Vp, *Ap;
    cudaGetSymbolAddress((void**)&Qp, g_Q);
    cudaGetSymbolAddress((void**)&Kp, g_K);
    cudaGetSymbolAddress((void**)&Vp, g_V);
    cudaGetSymbolAddress((void**)&Ap, g_A);

    static bool attr_set = false;
    if (!attr_set) {
        cudaFuncSetAttribute(gemm_tf32,
                             cudaFuncAttributeMaxDynamicSharedMemorySize,
                             GEMM_SMEM);
        cudaFuncSetAttribute(attn_kernel,
                             cudaFuncAttributeMaxDynamicSharedMemorySize,
                             114688);
        attr_set = true;
    }

    dim3 gg(GN / 128, MROWS / 128);  // (16, 32)
    gemm_tf32<<<gg, 256, GEMM_SMEM>>>(x, Wq, Qp);
    gemm_tf32<<<gg, 256, GEMM_SMEM>>>(x, Wk, Kp);
    gemm_tf32<<<gg, 256, GEMM_SMEM>>>(x, Wv, Vp);

    rope_tab_kernel<<<(SEQ * 64) / 256, 256>>>();
    rope_apply_kernel<<<(BATCH * SEQ * NH * 64) / 256, 256>>>(Qp, Kp);

    attn_kernel<<<dim3(SEQ / 64, BATCH * NH), 256, 114688>>>();

    gemm_tf32<<<gg, 256, GEMM_SMEM>>>(Ap, Wo, out);
}

// round 5
// speedup vs baseline: 1.7396x; 1.2134x over previous
#include <cuda_runtime.h>
#include <cuda_fp16.h>
#include <math.h>
#include <stdint.h>

#define BATCH 2
#define SEQ   2048
#define CH    2048
#define NH    16
#define HD    128
#define WIN   512
#define MROWS (BATCH*SEQ)   // 4096

// ---------------- scratch (static device globals) ---------------------------
__device__ float  g_Q[MROWS*CH];
__device__ float  g_K[MROWS*CH];
__device__ float  g_V[MROWS*CH];
__device__ __half g_Xh[MROWS*CH];
__device__ __half g_Wh[4][CH*CH];     // transposed weights, [n][k], fp16
__device__ __half g_Ah[MROWS*CH];     // attention output, fp16
__device__ float  g_cos[SEQ*64];
__device__ float  g_sin[SEQ*64];

// ---------------- helpers ---------------------------------------------------
__device__ __forceinline__ unsigned long long pack2(float lo, float hi) {
    unsigned long long r;
    asm("mov.b64 %0, {%1, %2};" : "=l"(r) : "f"(lo), "f"(hi));
    return r;
}
__device__ __forceinline__ float2 unpack2(unsigned long long v) {
    float2 f;
    asm("mov.b64 {%0, %1}, %2;" : "=f"(f.x), "=f"(f.y) : "l"(v));
    return f;
}
__device__ __forceinline__ unsigned long long ffma2(unsigned long long a,
                                                    unsigned long long b,
                                                    unsigned long long c) {
    unsigned long long d;
    asm("fma.rn.f32x2 %0, %1, %2, %3;" : "=l"(d) : "l"(a), "l"(b), "l"(c));
    return d;
}
__device__ __forceinline__ unsigned long long fmul2(unsigned long long a,
                                                    unsigned long long b) {
    unsigned long long d;
    asm("mul.rn.f32x2 %0, %1, %2;" : "=l"(d) : "l"(a), "l"(b));
    return d;
}
__device__ __forceinline__ uint32_t s2u(const void* p) {
    uint32_t a;
    asm("{ .reg .u64 t; cvta.to.shared.u64 t, %1; cvt.u32.u64 %0, t; }"
        : "=r"(a) : "l"(p));
    return a;
}
__device__ __forceinline__ void cpa16(uint32_t dst, const void* src) {
    asm volatile("cp.async.cg.shared.global [%0], [%1], 16;" :: "r"(dst), "l"(src));
}
__device__ __forceinline__ void ldm4(uint32_t* r, uint32_t addr) {
    asm volatile("ldmatrix.sync.aligned.m8n8.x4.shared.b16 {%0,%1,%2,%3}, [%4];"
        : "=r"(r[0]), "=r"(r[1]), "=r"(r[2]), "=r"(r[3]) : "r"(addr));
}
__device__ __forceinline__ void mma16(float* d, const uint32_t* a, const uint32_t* b) {
    asm volatile(
        "mma.sync.aligned.m16n8k16.row.col.f32.f16.f16.f32 "
        "{%0,%1,%2,%3}, {%4,%5,%6,%7}, {%8,%9}, {%0,%1,%2,%3};"
        : "+f"(d[0]), "+f"(d[1]), "+f"(d[2]), "+f"(d[3])
        : "r"(a[0]), "r"(a[1]), "r"(a[2]), "r"(a[3]), "r"(b[0]), "r"(b[1]));
}

// ---------------- fp16 mma GEMM ---------------------------------------------
// C[4096,2048](f32) = Ah[4096,2048(K)] x Bh[2048(N),2048(K)]^T, both fp16 K-major.
// 128x128 tile/CTA, BK=64 (128B fp16 rows, SW128 swizzle), 4-stage cp.async.
// 8 warps (2x4), warp tile 64x32: 4 m16 x 4 n8 mma tiles, 4 k16 steps/stage.
#define NST 4
#define STG_B 32768                    // 16KB A + 16KB B per stage
#define GEMM_SMEM (NST*STG_B)          // 131072

__global__ __launch_bounds__(256) void gemm_h(const __half* __restrict__ Ah,
                                              const __half* __restrict__ Bh,
                                              float* __restrict__ C) {
    extern __shared__ char smem[];
    const uint32_t sb = s2u(smem);
    const int tid  = threadIdx.x;
    const int lane = tid & 31;
    const int wid  = tid >> 5;
    const int wm   = (wid >> 2) * 64;
    const int wn   = (wid & 3) * 32;
    const int row0 = blockIdx.y * 128;
    const int col0 = blockIdx.x * 128;

    float acc[4][4][4];
    #pragma unroll
    for (int i = 0; i < 4; i++)
        #pragma unroll
        for (int j = 0; j < 4; j++)
            #pragma unroll
            for (int r = 0; r < 4; r++) acc[i][j][r] = 0.0f;

    auto load_stage = [&](int slot, int kt) {
        uint32_t ab = sb + slot * STG_B;
        uint32_t bb = ab + 16384;
        #pragma unroll
        for (int i = 0; i < 4; i++) {
            int idx = tid + i * 256;          // 0..1023
            int row = idx >> 3, ch = idx & 7; // row 0..127, 16B chunk 0..7
            uint32_t off = row * 128 + ch * 16;
            uint32_t sw = off ^ ((off >> 3) & 0x70);
            cpa16(ab + sw, Ah + (size_t)(row0 + row) * CH + kt + ch * 8);
            cpa16(bb + sw, Bh + (size_t)(col0 + row) * CH + kt + ch * 8);
        }
    };
    auto compute = [&](int slot) {
        uint32_t ab = sb + slot * STG_B;
        uint32_t bb = ab + 16384;
        #pragma unroll
        for (int ks = 0; ks < 4; ks++) {
            uint32_t aF[4][4], bF[4][2];
            #pragma unroll
            for (int i = 0; i < 4; i++) {
                int row = wm + i * 16 + (lane & 15);
                uint32_t off = row * 128 + ks * 32 + ((lane >> 4) << 4);
                ldm4(aF[i], ab + (off ^ ((off >> 3) & 0x70)));
            }
            #pragma unroll
            for (int j2 = 0; j2 < 2; j2++) {
                int row = wn + j2 * 16 + ((lane >> 4) << 3) + (lane & 7);
                uint32_t off = row * 128 + ks * 32 + (((lane >> 3) & 1) << 4);
                uint32_t r[4];
                ldm4(r, bb + (off ^ ((off >> 3) & 0x70)));
                bF[2 * j2][0] = r[0];  bF[2 * j2][1] = r[1];
                bF[2 * j2 + 1][0] = r[2];  bF[2 * j2 + 1][1] = r[3];
            }
            #pragma unroll
            for (int i = 0; i < 4; i++)
                #pragma unroll
                for (int j = 0; j < 4; j++)
                    mma16(acc[i][j], aF[i], bF[j]);
        }
    };

    load_stage(0, 0);
    asm volatile("cp.async.commit_group;" ::: "memory");
    load_stage(1, 64);
    asm volatile("cp.async.commit_group;" ::: "memory");
    load_stage(2, 128);
    asm volatile("cp.async.commit_group;" ::: "memory");

    #pragma unroll 1
    for (int it = 0; it < 32; it++) {
        asm volatile("cp.async.wait_group 2;" ::: "memory");
        __syncthreads();
        int jn = it + 3;
        if (jn < 32) load_stage(jn & 3, jn * 64);
        asm volatile("cp.async.commit_group;" ::: "memory");
        compute(it & 3);
    }

    #pragma unroll
    for (int i = 0; i < 4; i++) {
        #pragma unroll
        for (int j = 0; j < 4; j++) {
            int r = row0 + wm + i * 16 + (lane >> 2);
            int c = col0 + wn + j * 8 + 2 * (lane & 3);
            *(float2*)&C[(size_t)r * CH + c] =
                make_float2(acc[i][j][0], acc[i][j][1]);
            *(float2*)&C[(size_t)(r + 8) * CH + c] =
                make_float2(acc[i][j][2], acc[i][j][3]);
        }
    }
}

// ---------------- prep: fp32 -> fp16 conversions -----------------------------
__global__ __launch_bounds__(256) void f32_to_f16(const float4* __restrict__ in,
                                                  __half* __restrict__ out) {
    int i = blockIdx.x * blockDim.x + threadIdx.x;
    float4 v = in[i];
    __half2 h0 = __floats2half2_rn(v.x, v.y);
    __half2 h1 = __floats2half2_rn(v.z, v.w);
    uint2 u = make_uint2(*(uint32_t*)&h0, *(uint32_t*)&h1);
    ((uint2*)out)[i] = u;
}

__global__ __launch_bounds__(256) void transpose_h(const float* __restrict__ W,
                                                   __half* __restrict__ Wt) {
    __shared__ float t[32][33];
    int bx = blockIdx.x * 32;   // k base
    int by = blockIdx.y * 32;   // n base
    int tx = threadIdx.x & 31, ty = threadIdx.x >> 5;
    #pragma unroll
    for (int i = 0; i < 4; i++)
        t[ty + 8 * i][tx] = W[(size_t)(bx + ty + 8 * i) * CH + by + tx];
    __syncthreads();
    int r = threadIdx.x >> 3;          // 0..31  (n within tile)
    int c2 = threadIdx.x & 7;          // 0..7   (half2 col pair)
    #pragma unroll
    for (int p = 0; p < 2; p++) {
        int cc = c2 + p * 8;           // half2 index 0..15
        __half2 h = __floats2half2_rn(t[2 * cc][r], t[2 * cc + 1][r]);
        ((__half2*)(Wt + (size_t)(by + r) * CH + bx))[cc] = h;
    }
}

// ---------------- RoPE -------------------------------------------------------
__global__ __launch_bounds__(256) void rope_tab_kernel() {
    int idx = blockIdx.x * blockDim.x + threadIdx.x;
    if (idx >= SEQ * 64) return;
    int d = idx & 63;
    int t = idx >> 6;
    double inv = exp(-((double)d / 64.0) * log(10000.0));
    double sd, cd;
    sincos((double)t * inv, &sd, &cd);
    g_cos[idx] = (float)cd;
    g_sin[idx] = (float)sd;
}

__global__ __launch_bounds__(256) void rope_apply_kernel(float* __restrict__ Q,
                                                         float* __restrict__ K) {
    int idx = blockIdx.x * blockDim.x + threadIdx.x;
    if (idx >= BATCH * SEQ * NH * 64) return;
    int d = idx & 63;
    int h = (idx >> 6) & (NH - 1);
    int t = (idx >> 10) & (SEQ - 1);
    int b = idx >> 21;

    float c = g_cos[(t << 6) + d];
    float s = g_sin[(t << 6) + d];

    size_t base = ((size_t)(b * SEQ + t)) * CH + h * HD + d;
    float q1 = Q[base], q2 = Q[base + 64];
    Q[base]      = q1 * c - q2 * s;
    Q[base + 64] = q1 * s + q2 * c;
    float k1 = K[base], k2 = K[base + 64];
    K[base]      = k1 * c - k2 * s;
    K[base + 64] = k1 * s + k2 * c;
}

// ---------------- Attention (flash-style, inverted-window mask) ------------
__global__ __launch_bounds__(256) void attn_kernel() {
    extern __shared__ float smA[];
    float* Qs = smA;
    float* Ks = smA + 8192;
    float* Vs = smA + 16384;
    float* Ps = smA + 24576;

    const int bh = blockIdx.y;
    const int b = bh >> 4;
    const int h = bh & 15;
    const int qbase = blockIdx.x * 64;
    const int tid = threadIdx.x;
    const int tx = tid & 15;
    const int ty = tid >> 4;
    const float scale = 0.08838834764831845f;  // 1/sqrt(128)

    const float* Qg = g_Q + (size_t)(b * SEQ) * CH + h * HD;
    const float* Kg = g_K + (size_t)(b * SEQ) * CH + h * HD;
    const float* Vg = g_V + (size_t)(b * SEQ) * CH + h * HD;

    for (int idx = tid; idx < 64 * 32; idx += 256) {
        int r = idx >> 5, c4 = (idx & 31) << 2;
        *(float4*)&Qs[r * 128 + c4] =
            *(const float4*)&Qg[(size_t)(qbase + r) * CH + c4];
    }

    float mrow[4], lrow[4];
    unsigned long long acc[4][4];
    #pragma unroll
    for (int i = 0; i < 4; i++) {
        mrow[i] = -1e30f;
        lrow[i] = 0.0f;
        #pragma unroll
        for (int j = 0; j < 4; j++) acc[i][j] = 0ull;
    }
    __syncthreads();

    for (int kb = 0; kb < SEQ; kb += 64) {
        bool skip = (kb + 63 <= qbase) && (kb >= qbase + 63 - (WIN - 1));
        if (skip) continue;

        for (int idx = tid; idx < 64 * 32; idx += 256) {
            int r = idx >> 5, c4 = (idx & 31) << 2;
            *(float4*)&Ks[r * 128 + c4] =
                *(const float4*)&Kg[(size_t)(kb + r) * CH + c4];
            *(float4*)&Vs[r * 128 + c4] =
                *(const float4*)&Vg[(size_t)(kb + r) * CH + c4];
        }
        __syncthreads();

        float s[4][4] = {};
        #pragma unroll 8
        for (int d4 = 0; d4 < 128; d4 += 4) {
            float4 q[4], k[4];
            #pragma unroll
            for (int ii = 0; ii < 4; ii++)
                q[ii] = *(const float4*)&Qs[(ty * 4 + ii) * 128 + d4];
            #pragma unroll
            for (int jj = 0; jj < 4; jj++)
                k[jj] = *(const float4*)&Ks[(tx * 4 + jj) * 128 + d4];
            #pragma unroll
            for (int ii = 0; ii < 4; ii++)
                #pragma unroll
                for (int jj = 0; jj < 4; jj++) {
                    s[ii][jj] += q[ii].x * k[jj].x;
                    s[ii][jj] += q[ii].y * k[jj].y;
                    s[ii][jj] += q[ii].z * k[jj].z;
                    s[ii][jj] += q[ii].w * k[jj].w;
                }
        }

        #pragma unroll
        for (int ii = 0; ii < 4; ii++) {
            int i = qbase + ty * 4 + ii;
            #pragma unroll
            for (int jj = 0; jj < 4; jj++) {
                int j = kb + tx * 4 + jj;
                float v = s[ii][jj] * scale;
                bool masked = (j <= i) && (j >= i - (WIN - 1));
                s[ii][jj] = masked ? -1e30f : v;
            }
        }

        #pragma unroll
        for (int ii = 0; ii < 4; ii++) {
            float rmax = fmaxf(fmaxf(s[ii][0], s[ii][1]),
                               fmaxf(s[ii][2], s[ii][3]));
            #pragma unroll
            for (int m = 1; m < 16; m <<= 1)
                rmax = fmaxf(rmax, __shfl_xor_sync(0xffffffffu, rmax, m));
            float mnew = fmaxf(mrow[ii], rmax);
            float corr = __expf(mrow[ii] - mnew);
            float psum = 0.0f;
            #pragma unroll
            for (int jj = 0; jj < 4; jj++) {
                float p = __expf(s[ii][jj] - mnew);
                s[ii][jj] = p;
                psum += p;
            }
            #pragma unroll
            for (int m = 1; m < 16; m <<= 1)
                psum += __shfl_xor_sync(0xffffffffu, psum, m);
            lrow[ii] = lrow[ii] * corr + psum;
            mrow[ii] = mnew;
            unsigned long long cp = pack2(corr, corr);
            #pragma unroll
            for (int j2 = 0; j2 < 4; j2++)
                acc[ii][j2] = fmul2(acc[ii][j2], cp);
            #pragma unroll
            for (int jj = 0; jj < 4; jj++)
                Ps[(ty * 4 + ii) * 64 + tx * 4 + jj] = s[ii][jj];
        }
        __syncthreads();

        #pragma unroll 8
        for (int kk = 0; kk < 64; kk++) {
            float p[4];
            #pragma unroll
            for (int ii = 0; ii < 4; ii++)
                p[ii] = Ps[(ty * 4 + ii) * 64 + kk];
            unsigned long long vp[4];
            #pragma unroll
            for (int j2 = 0; j2 < 4; j2++)
                vp[j2] = *(const unsigned long long*)&Vs[kk * 128 + tx * 8 + 2 * j2];
            #pragma unroll
            for (int ii = 0; ii < 4; ii++) {
                unsigned long long pp = pack2(p[ii], p[ii]);
                #pragma unroll
                for (int j2 = 0; j2 < 4; j2++)
                    acc[ii][j2] = ffma2(pp, vp[j2], acc[ii][j2]);
            }
        }
        __syncthreads();
    }

    // epilogue: normalize + emit fp16 (feeds fp16 O-projection GEMM)
    __half* Og = g_Ah + (size_t)(b * SEQ) * CH + h * HD;
    #pragma unroll
    for (int ii = 0; ii < 4; ii++) {
        float inv_l = 1.0f / lrow[ii];
        size_t rbase = (size_t)(qbase + ty * 4 + ii) * CH + tx * 8;
        #pragma unroll
        for (int j2 = 0; j2 < 4; j2++) {
            float2 v = unpack2(acc[ii][j2]);
            __half2 hh = __floats2half2_rn(v.x * inv_l, v.y * inv_l);
            *(__half2*)&Og[rbase + 2 * j2] = hh;
        }
    }
}

// ---------------- launch ----------------------------------------------------
extern "C" void kernel_launch(void* const* d_in, const int* in_sizes, int n_in,
                              void* d_out, int out_size) {
    const float* x  = (const float*)d_in[0];
    const float* Wq = (const float*)d_in[1];
    const float* Wk = (const float*)d_in[2];
    const float* Wv = (const float*)d_in[3];
    const float* Wo = (const float*)d_in[4];
    float* out = (float*)d_out;

    float *Qp, *Kp, *Vp;
    __half *Xh, *Wh, *Ahp;
    cudaGetSymbolAddress((void**)&Qp, g_Q);
    cudaGetSymbolAddress((void**)&Kp, g_K);
    cudaGetSymbolAddress((void**)&Vp, g_V);
    cudaGetSymbolAddress((void**)&Xh, g_Xh);
    cudaGetSymbolAddress((void**)&Wh, g_Wh);
    cudaGetSymbolAddress((void**)&Ahp, g_Ah);
    __half* Wh0 = Wh;
    __half* Wh1 = Wh + (size_t)CH * CH;
    __half* Wh2 = Wh + 2 * (size_t)CH * CH;
    __half* Wh3 = Wh + 3 * (size_t)CH * CH;

    static bool attr_set = false;
    if (!attr_set) {
        cudaFuncSetAttribute(gemm_h,
                             cudaFuncAttributeMaxDynamicSharedMemorySize,
                             GEMM_SMEM);
        cudaFuncSetAttribute(attn_kernel,
                             cudaFuncAttributeMaxDynamicSharedMemorySize,
                             114688);
        attr_set = true;
    }

    // prep: convert x, transpose+convert weights
    f32_to_f16<<<(MROWS * CH / 4) / 256, 256>>>((const float4*)x, Xh);
    dim3 tg(CH / 32, CH / 32);
    transpose_h<<<tg, 256>>>(Wq, Wh0);
    transpose_h<<<tg, 256>>>(Wk, Wh1);
    transpose_h<<<tg, 256>>>(Wv, Wh2);
    transpose_h<<<tg, 256>>>(Wo, Wh3);

    dim3 gg(CH / 128, MROWS / 128);  // (16, 32)
    gemm_h<<<gg, 256, GEMM_SMEM>>>(Xh, Wh0, Qp);
    gemm_h<<<gg, 256, GEMM_SMEM>>>(Xh, Wh1, Kp);
    gemm_h<<<gg, 256, GEMM_SMEM>>>(Xh, Wh2, Vp);

    rope_tab_kernel<<<(SEQ * 64) / 256, 256>>>();
    rope_apply_kernel<<<(BATCH * SEQ * NH * 64) / 256, 256>>>(Qp, Kp);

    attn_kernel<<<dim3(SEQ / 64, BATCH * NH), 256, 114688>>>();

    gemm_h<<<gg, 256, GEMM_SMEM>>>(Ahp, Wh3, out);
}

// round 6
// speedup vs baseline: 11.2529x; 6.4688x over previous
#include <cuda_runtime.h>
#include <cuda_fp16.h>
#include <math.h>
#include <stdint.h>

#define BATCH 2
#define SEQ   2048
#define CH    2048
#define NH    16
#define HD    128
#define WIN   512
#define MROWS (BATCH*SEQ)   // 4096

// ---------------- scratch (static device globals) ---------------------------
__device__ float  g_QKV[3][MROWS*CH];     // fp32 projection outputs
__device__ __half g_Xh[MROWS*CH];
__device__ __half g_Wh[4][CH*CH];         // transposed weights [n][k] fp16
__device__ __half g_Qh[MROWS*CH];
__device__ __half g_Kh[MROWS*CH];
__device__ __half g_Vh[MROWS*CH];
__device__ __half g_Ah[MROWS*CH];         // attention output fp16
__device__ float  g_cos[SEQ*64];
__device__ float  g_sin[SEQ*64];

// ---------------- helpers ---------------------------------------------------
__device__ __forceinline__ uint32_t s2u(const void* p) {
    uint32_t a;
    asm("{ .reg .u64 t; cvta.to.shared.u64 t, %1; cvt.u32.u64 %0, t; }"
        : "=r"(a) : "l"(p));
    return a;
}
__device__ __forceinline__ void cpa16(uint32_t dst, const void* src) {
    asm volatile("cp.async.cg.shared.global [%0], [%1], 16;" :: "r"(dst), "l"(src));
}
__device__ __forceinline__ void ldm4(uint32_t* r, uint32_t addr) {
    asm volatile("ldmatrix.sync.aligned.m8n8.x4.shared.b16 {%0,%1,%2,%3}, [%4];"
        : "=r"(r[0]), "=r"(r[1]), "=r"(r[2]), "=r"(r[3]) : "r"(addr));
}
__device__ __forceinline__ void ldm4t(uint32_t* r, uint32_t addr) {
    asm volatile("ldmatrix.sync.aligned.m8n8.x4.trans.shared.b16 {%0,%1,%2,%3}, [%4];"
        : "=r"(r[0]), "=r"(r[1]), "=r"(r[2]), "=r"(r[3]) : "r"(addr));
}
__device__ __forceinline__ void mma16(float* d, const uint32_t* a, const uint32_t* b) {
    asm volatile(
        "mma.sync.aligned.m16n8k16.row.col.f32.f16.f16.f32 "
        "{%0,%1,%2,%3}, {%4,%5,%6,%7}, {%8,%9}, {%0,%1,%2,%3};"
        : "+f"(d[0]), "+f"(d[1]), "+f"(d[2]), "+f"(d[3])
        : "r"(a[0]), "r"(a[1]), "r"(a[2]), "r"(a[3]), "r"(b[0]), "r"(b[1]));
}
__device__ __forceinline__ uint32_t h2pack(float a, float b) {
    __half2 h = __floats2half2_rn(a, b);
    return *(uint32_t*)&h;
}

// ---------------- fp16 mma GEMM (also used fused-QKV via gridDim.z) ---------
#define NST 4
#define STG_B 32768
#define GEMM_SMEM (NST*STG_B)

__global__ __launch_bounds__(256) void gemm_h(const __half* __restrict__ Ah,
                                              const __half* __restrict__ Bh0,
                                              float* __restrict__ C0) {
    extern __shared__ char smem[];
    const __half* Bh = Bh0 + (size_t)blockIdx.z * CH * CH;
    float* C = C0 + (size_t)blockIdx.z * MROWS * CH;
    const uint32_t sb = s2u(smem);
    const int tid  = threadIdx.x;
    const int lane = tid & 31;
    const int wid  = tid >> 5;
    const int wm   = (wid >> 2) * 64;
    const int wn   = (wid & 3) * 32;
    const int row0 = blockIdx.y * 128;
    const int col0 = blockIdx.x * 128;

    float acc[4][4][4];
    #pragma unroll
    for (int i = 0; i < 4; i++)
        #pragma unroll
        for (int j = 0; j < 4; j++)
            #pragma unroll
            for (int r = 0; r < 4; r++) acc[i][j][r] = 0.0f;

    auto load_stage = [&](int slot, int kt) {
        uint32_t ab = sb + slot * STG_B;
        uint32_t bb = ab + 16384;
        #pragma unroll
        for (int i = 0; i < 4; i++) {
            int idx = tid + i * 256;
            int row = idx >> 3, ch = idx & 7;
            uint32_t off = row * 128 + ch * 16;
            uint32_t sw = off ^ ((off >> 3) & 0x70);
            cpa16(ab + sw, Ah + (size_t)(row0 + row) * CH + kt + ch * 8);
            cpa16(bb + sw, Bh + (size_t)(col0 + row) * CH + kt + ch * 8);
        }
    };
    auto compute = [&](int slot) {
        uint32_t ab = sb + slot * STG_B;
        uint32_t bb = ab + 16384;
        #pragma unroll
        for (int ks = 0; ks < 4; ks++) {
            uint32_t aF[4][4], bF[4][2];
            #pragma unroll
            for (int i = 0; i < 4; i++) {
                int row = wm + i * 16 + (lane & 15);
                uint32_t off = row * 128 + ks * 32 + ((lane >> 4) << 4);
                ldm4(aF[i], ab + (off ^ ((off >> 3) & 0x70)));
            }
            #pragma unroll
            for (int j2 = 0; j2 < 2; j2++) {
                int row = wn + j2 * 16 + ((lane >> 4) << 3) + (lane & 7);
                uint32_t off = row * 128 + ks * 32 + (((lane >> 3) & 1) << 4);
                uint32_t r[4];
                ldm4(r, bb + (off ^ ((off >> 3) & 0x70)));
                bF[2 * j2][0] = r[0];  bF[2 * j2][1] = r[1];
                bF[2 * j2 + 1][0] = r[2];  bF[2 * j2 + 1][1] = r[3];
            }
            #pragma unroll
            for (int i = 0; i < 4; i++)
                #pragma unroll
                for (int j = 0; j < 4; j++)
                    mma16(acc[i][j], aF[i], bF[j]);
        }
    };

    load_stage(0, 0);
    asm volatile("cp.async.commit_group;" ::: "memory");
    load_stage(1, 64);
    asm volatile("cp.async.commit_group;" ::: "memory");
    load_stage(2, 128);
    asm volatile("cp.async.commit_group;" ::: "memory");

    #pragma unroll 1
    for (int it = 0; it < 32; it++) {
        asm volatile("cp.async.wait_group 2;" ::: "memory");
        __syncthreads();
        int jn = it + 3;
        if (jn < 32) load_stage(jn & 3, jn * 64);
        asm volatile("cp.async.commit_group;" ::: "memory");
        compute(it & 3);
    }

    #pragma unroll
    for (int i = 0; i < 4; i++) {
        #pragma unroll
        for (int j = 0; j < 4; j++) {
            int r = row0 + wm + i * 16 + (lane >> 2);
            int c = col0 + wn + j * 8 + 2 * (lane & 3);
            *(float2*)&C[(size_t)r * CH + c] =
                make_float2(acc[i][j][0], acc[i][j][1]);
            *(float2*)&C[(size_t)(r + 8) * CH + c] =
                make_float2(acc[i][j][2], acc[i][j][3]);
        }
    }
}

// ---------------- prep -------------------------------------------------------
__global__ __launch_bounds__(256) void f32_to_f16(const float4* __restrict__ in,
                                                  __half* __restrict__ out) {
    int i = blockIdx.x * blockDim.x + threadIdx.x;
    float4 v = in[i];
    __half2 h0 = __floats2half2_rn(v.x, v.y);
    __half2 h1 = __floats2half2_rn(v.z, v.w);
    uint2 u = make_uint2(*(uint32_t*)&h0, *(uint32_t*)&h1);
    ((uint2*)out)[i] = u;
}

__global__ __launch_bounds__(256) void transpose_h(const float* __restrict__ W,
                                                   __half* __restrict__ Wt) {
    __shared__ float t[32][33];
    int bx = blockIdx.x * 32;
    int by = blockIdx.y * 32;
    int tx = threadIdx.x & 31, ty = threadIdx.x >> 5;
    #pragma unroll
    for (int i = 0; i < 4; i++)
        t[ty + 8 * i][tx] = W[(size_t)(bx + ty + 8 * i) * CH + by + tx];
    __syncthreads();
    int r = threadIdx.x >> 3;
    int c2 = threadIdx.x & 7;
    #pragma unroll
    for (int p = 0; p < 2; p++) {
        int cc = c2 + p * 8;
        __half2 h = __floats2half2_rn(t[2 * cc][r], t[2 * cc + 1][r]);
        ((__half2*)(Wt + (size_t)(by + r) * CH + bx))[cc] = h;
    }
}

// ---------------- RoPE + fp16 emission ---------------------------------------
__global__ __launch_bounds__(256) void rope_tab_kernel() {
    int idx = blockIdx.x * blockDim.x + threadIdx.x;
    if (idx >= SEQ * 64) return;
    int d = idx & 63;
    int t = idx >> 6;
    double inv = exp(-((double)d / 64.0) * log(10000.0));
    double sd, cd;
    sincos((double)t * inv, &sd, &cd);
    g_cos[idx] = (float)cd;
    g_sin[idx] = (float)sd;
}

__global__ __launch_bounds__(256) void rope_apply_kernel() {
    int idx = blockIdx.x * blockDim.x + threadIdx.x;
    if (idx >= BATCH * SEQ * NH * 64) return;
    int d = idx & 63;
    int h = (idx >> 6) & (NH - 1);
    int t = (idx >> 10) & (SEQ - 1);
    int b = idx >> 21;

    float c = g_cos[(t << 6) + d];
    float s = g_sin[(t << 6) + d];

    size_t base = ((size_t)(b * SEQ + t)) * CH + h * HD + d;
    float q1 = g_QKV[0][base], q2 = g_QKV[0][base + 64];
    g_Qh[base]      = __float2half(q1 * c - q2 * s);
    g_Qh[base + 64] = __float2half(q1 * s + q2 * c);
    float k1 = g_QKV[1][base], k2 = g_QKV[1][base + 64];
    g_Kh[base]      = __float2half(k1 * c - k2 * s);
    g_Kh[base + 64] = __float2half(k1 * s + k2 * c);
    g_Vh[base]      = __float2half(g_QKV[2][base]);
    g_Vh[base + 64] = __float2half(g_QKV[2][base + 64]);
}

// ---------------- Attention: fp16 mma flash, inverted-window mask -----------
// CTA: 64 q rows, 128 threads (4 warps), warp owns 16 full rows.
// smem halves: Qs[64][136] | stage{0,1}: Ks[64][136], Vs[64][136]
#define ATS 136                     // padded row stride (halves)
#define Q_OFF 0
#define KV_OFF (64*ATS)             // 8704 halves
#define STAGE_H (2*64*ATS)          // K+V per stage, 17408 halves
#define ATT_SMEM ((64*ATS + 2*STAGE_H)*2)   // 87040 bytes

__device__ __forceinline__ int next_act(int kb, int q0) {
    do { kb += 64; } while (kb < SEQ && (kb + 63 <= q0) && (kb >= q0 - (WIN - 64)));
    return kb;
}

__global__ __launch_bounds__(128) void attn_mma_kernel() {
    extern __shared__ char smem[];
    const uint32_t sb = s2u(smem);
    const int bh = blockIdx.y;
    const int b = bh >> 4;
    const int h = bh & 15;
    const int q0 = blockIdx.x * 64;
    const int tid = threadIdx.x;
    const int lane = tid & 31;
    const int w = tid >> 5;
    const float scale = 0.08838834764831845f;

    const __half* Qg = g_Qh + ((size_t)(b * SEQ) + q0) * CH + h * HD;

    auto load_kv = [&](int stage, int kb) {
        const __half* Kg = g_Kh + ((size_t)(b * SEQ) + kb) * CH + h * HD;
        const __half* Vg = g_Vh + ((size_t)(b * SEQ) + kb) * CH + h * HD;
        uint32_t kbB = sb + (KV_OFF + stage * STAGE_H) * 2;
        uint32_t vbB = kbB + 64 * ATS * 2;
        #pragma unroll
        for (int i = 0; i < 8; i++) {
            int idx = tid + i * 128;
            int row = idx >> 4, ch = idx & 15;
            uint32_t d = (row * ATS + ch * 8) * 2;
            cpa16(kbB + d, Kg + (size_t)row * CH + ch * 8);
            cpa16(vbB + d, Vg + (size_t)row * CH + ch * 8);
        }
    };

    // Q load folded into group 0
    {
        #pragma unroll
        for (int i = 0; i < 8; i++) {
            int idx = tid + i * 128;
            int row = idx >> 4, ch = idx & 15;
            cpa16(sb + (row * ATS + ch * 8) * 2, Qg + (size_t)row * CH + ch * 8);
        }
    }

    int cur = next_act(-64, q0);
    load_kv(0, cur);
    asm volatile("cp.async.commit_group;" ::: "memory");
    int nxt = next_act(cur, q0);
    if (nxt < SEQ) load_kv(1, nxt);
    asm volatile("cp.async.commit_group;" ::: "memory");
    int nn = (nxt < SEQ) ? next_act(nxt, q0) : SEQ;

    float m0 = -1e30f, m1 = -1e30f, l0 = 0.0f, l1 = 0.0f;
    float oacc[16][4];
    #pragma unroll
    for (int t = 0; t < 16; t++)
        #pragma unroll
        for (int r = 0; r < 4; r++) oacc[t][r] = 0.0f;

    int stage = 0;
    #pragma unroll 1
    while (cur < SEQ) {
        asm volatile("cp.async.wait_group 1;" ::: "memory");
        __syncthreads();

        uint32_t kbB = sb + (KV_OFF + stage * STAGE_H) * 2;
        uint32_t vbB = kbB + 64 * ATS * 2;

        // ---- S = Q K^T ----
        float sacc[8][4];
        #pragma unroll
        for (int t = 0; t < 8; t++)
            #pragma unroll
            for (int r = 0; r < 4; r++) sacc[t][r] = 0.0f;

        #pragma unroll
        for (int ks = 0; ks < 8; ks++) {
            uint32_t aF[4];
            {
                int row = 16 * w + (lane & 15);
                uint32_t off = (row * ATS + ks * 16 + 8 * (lane >> 4)) * 2;
                ldm4(aF, sb + off);
            }
            #pragma unroll
            for (int jp = 0; jp < 4; jp++) {
                int row = 16 * jp + ((lane >> 4) << 3) + (lane & 7);
                uint32_t off = (row * ATS + ks * 16 + 8 * ((lane >> 3) & 1)) * 2;
                uint32_t r[4];
                ldm4(r, kbB + off);
                mma16(sacc[2 * jp],     aF, r);
                mma16(sacc[2 * jp + 1], aF, r + 2);
            }
        }

        // ---- scale + mask ----
        int i0 = q0 + 16 * w + (lane >> 2);
        int i1 = i0 + 8;
        #pragma unroll
        for (int t = 0; t < 8; t++) {
            int j0 = cur + 8 * t + 2 * (lane & 3);
            #pragma unroll
            for (int e = 0; e < 2; e++) {
                int j = j0 + e;
                float v0 = sacc[t][e] * scale;
                float v1 = sacc[t][2 + e] * scale;
                bool msk0 = (j <= i0) && (j >= i0 - (WIN - 1));
                bool msk1 = (j <= i1) && (j >= i1 - (WIN - 1));
                sacc[t][e]     = msk0 ? -1e30f : v0;
                sacc[t][2 + e] = msk1 ? -1e30f : v1;
            }
        }

        // ---- online softmax (rows i0, i1) ----
        float rmax0 = -1e30f, rmax1 = -1e30f;
        #pragma unroll
        for (int t = 0; t < 8; t++) {
            rmax0 = fmaxf(rmax0, fmaxf(sacc[t][0], sacc[t][1]));
            rmax1 = fmaxf(rmax1, fmaxf(sacc[t][2], sacc[t][3]));
        }
        rmax0 = fmaxf(rmax0, __shfl_xor_sync(0xffffffffu, rmax0, 1));
        rmax0 = fmaxf(rmax0, __shfl_xor_sync(0xffffffffu, rmax0, 2));
        rmax1 = fmaxf(rmax1, __shfl_xor_sync(0xffffffffu, rmax1, 1));
        rmax1 = fmaxf(rmax1, __shfl_xor_sync(0xffffffffu, rmax1, 2));
        float mn0 = fmaxf(m0, rmax0), mn1 = fmaxf(m1, rmax1);
        float cr0 = __expf(m0 - mn0), cr1 = __expf(m1 - mn1);
        float ps0 = 0.0f, ps1 = 0.0f;
        #pragma unroll
        for (int t = 0; t < 8; t++) {
            sacc[t][0] = __expf(sacc[t][0] - mn0);
            sacc[t][1] = __expf(sacc[t][1] - mn0);
            sacc[t][2] = __expf(sacc[t][2] - mn1);
            sacc[t][3] = __expf(sacc[t][3] - mn1);
            ps0 += sacc[t][0] + sacc[t][1];
            ps1 += sacc[t][2] + sacc[t][3];
        }
        ps0 += __shfl_xor_sync(0xffffffffu, ps0, 1);
        ps0 += __shfl_xor_sync(0xffffffffu, ps0, 2);
        ps1 += __shfl_xor_sync(0xffffffffu, ps1, 1);
        ps1 += __shfl_xor_sync(0xffffffffu, ps1, 2);
        l0 = l0 * cr0 + ps0;  m0 = mn0;
        l1 = l1 * cr1 + ps1;  m1 = mn1;
        #pragma unroll
        for (int t = 0; t < 16; t++) {
            oacc[t][0] *= cr0;  oacc[t][1] *= cr0;
            oacc[t][2] *= cr1;  oacc[t][3] *= cr1;
        }

        // ---- P fragments (fp16) ----
        uint32_t aP[4][4];
        #pragma unroll
        for (int k2 = 0; k2 < 4; k2++) {
            aP[k2][0] = h2pack(sacc[2 * k2][0],     sacc[2 * k2][1]);
            aP[k2][1] = h2pack(sacc[2 * k2][2],     sacc[2 * k2][3]);
            aP[k2][2] = h2pack(sacc[2 * k2 + 1][0], sacc[2 * k2 + 1][1]);
            aP[k2][3] = h2pack(sacc[2 * k2 + 1][2], sacc[2 * k2 + 1][3]);
        }

        // ---- O += P V ----
        #pragma unroll
        for (int k2 = 0; k2 < 4; k2++) {
            #pragma unroll
            for (int dt = 0; dt < 8; dt++) {
                int row = 16 * k2 + ((lane >> 3) & 1) * 8 + (lane & 7);
                uint32_t off = (row * ATS + dt * 16 + ((lane >> 4) << 3)) * 2;
                uint32_t r[4];
                ldm4t(r, vbB + off);
                mma16(oacc[2 * dt],     aP[k2], r);
                mma16(oacc[2 * dt + 1], aP[k2], r + 2);
            }
        }

        __syncthreads();
        if (nn < SEQ) load_kv(stage, nn);
        asm volatile("cp.async.commit_group;" ::: "memory");
        cur = nxt;  nxt = nn;
        nn = (nn < SEQ) ? next_act(nn, q0) : SEQ;
        stage ^= 1;
    }

    // ---- epilogue ----
    float il0 = 1.0f / l0, il1 = 1.0f / l1;
    int r0 = q0 + 16 * w + (lane >> 2);
    __half* Og = g_Ah + (size_t)(b * SEQ) * CH + h * HD;
    #pragma unroll
    for (int t = 0; t < 16; t++) {
        int c = 8 * t + 2 * (lane & 3);
        __half2 h0 = __floats2half2_rn(oacc[t][0] * il0, oacc[t][1] * il0);
        __half2 h1 = __floats2half2_rn(oacc[t][2] * il1, oacc[t][3] * il1);
        *(__half2*)&Og[(size_t)r0 * CH + c] = h0;
        *(__half2*)&Og[(size_t)(r0 + 8) * CH + c] = h1;
    }
}

// ---------------- launch ----------------------------------------------------
extern "C" void kernel_launch(void* const* d_in, const int* in_sizes, int n_in,
                              void* d_out, int out_size) {
    const float* x  = (const float*)d_in[0];
    const float* Wq = (const float*)d_in[1];
    const float* Wk = (const float*)d_in[2];
    const float* Wv = (const float*)d_in[3];
    const float* Wo = (const float*)d_in[4];
    float* out = (float*)d_out;

    float* QKVp;
    __half *Xh, *Wh, *Ahp;
    cudaGetSymbolAddress((void**)&QKVp, g_QKV);
    cudaGetSymbolAddress((void**)&Xh, g_Xh);
    cudaGetSymbolAddress((void**)&Wh, g_Wh);
    cudaGetSymbolAddress((void**)&Ahp, g_Ah);
    __half* Wh3 = Wh + 3 * (size_t)CH * CH;

    static bool attr_set = false;
    if (!attr_set) {
        cudaFuncSetAttribute(gemm_h,
                             cudaFuncAttributeMaxDynamicSharedMemorySize,
                             GEMM_SMEM);
        cudaFuncSetAttribute(attn_mma_kernel,
                             cudaFuncAttributeMaxDynamicSharedMemorySize,
                             ATT_SMEM);
        attr_set = true;
    }

    f32_to_f16<<<(MROWS * CH / 4) / 256, 256>>>((const float4*)x, Xh);
    dim3 tg(CH / 32, CH / 32);
    transpose_h<<<tg, 256>>>(Wq, Wh);
    transpose_h<<<tg, 256>>>(Wk, Wh + (size_t)CH * CH);
    transpose_h<<<tg, 256>>>(Wv, Wh + 2 * (size_t)CH * CH);
    transpose_h<<<tg, 256>>>(Wo, Wh3);

    dim3 gq(CH / 128, MROWS / 128, 3);
    gemm_h<<<gq, 256, GEMM_SMEM>>>(Xh, Wh, QKVp);

    rope_tab_kernel<<<(SEQ * 64) / 256, 256>>>();
    rope_apply_kernel<<<(BATCH * SEQ * NH * 64) / 256, 256>>>();

    attn_mma_kernel<<<dim3(SEQ / 64, BATCH * NH), 128, ATT_SMEM>>>();

    dim3 gg(CH / 128, MROWS / 128, 1);
    gemm_h<<<gg, 256, GEMM_SMEM>>>(Ahp, Wh3, out);
}

// round 8
// speedup vs baseline: 13.2392x; 1.1765x over previous
#include <cuda_runtime.h>
#include <cuda_fp16.h>
#include <math.h>
#include <stdint.h>

#define BATCH 2
#define SEQ   2048
#define CH    2048
#define NH    16
#define HD    128
#define WIN   512
#define MROWS (BATCH*SEQ)   // 4096

// ---------------- scratch (static device globals) ---------------------------
__device__ __half g_Xh[MROWS*CH];
__device__ __half g_Wh[4][CH*CH];         // transposed weights [n][k] fp16
__device__ __half g_Qh[MROWS*CH];
__device__ __half g_Kh[MROWS*CH];
__device__ __half g_Vh[MROWS*CH];
__device__ __half g_Ah[MROWS*CH];         // attention output fp16
__device__ float  g_cos[SEQ*64];
__device__ float  g_sin[SEQ*64];

// ---------------- helpers ---------------------------------------------------
__device__ __forceinline__ uint32_t s2u(const void* p) {
    uint32_t a;
    asm("{ .reg .u64 t; cvta.to.shared.u64 t, %1; cvt.u32.u64 %0, t; }"
        : "=r"(a) : "l"(p));
    return a;
}
__device__ __forceinline__ void cpa16(uint32_t dst, const void* src) {
    asm volatile("cp.async.cg.shared.global [%0], [%1], 16;" :: "r"(dst), "l"(src));
}
__device__ __forceinline__ void ldm4(uint32_t* r, uint32_t addr) {
    asm volatile("ldmatrix.sync.aligned.m8n8.x4.shared.b16 {%0,%1,%2,%3}, [%4];"
        : "=r"(r[0]), "=r"(r[1]), "=r"(r[2]), "=r"(r[3]) : "r"(addr));
}
__device__ __forceinline__ void ldm4t(uint32_t* r, uint32_t addr) {
    asm volatile("ldmatrix.sync.aligned.m8n8.x4.trans.shared.b16 {%0,%1,%2,%3}, [%4];"
        : "=r"(r[0]), "=r"(r[1]), "=r"(r[2]), "=r"(r[3]) : "r"(addr));
}
__device__ __forceinline__ void mma16(float* d, const uint32_t* a, const uint32_t* b) {
    asm volatile(
        "mma.sync.aligned.m16n8k16.row.col.f32.f16.f16.f32 "
        "{%0,%1,%2,%3}, {%4,%5,%6,%7}, {%8,%9}, {%0,%1,%2,%3};"
        : "+f"(d[0]), "+f"(d[1]), "+f"(d[2]), "+f"(d[3])
        : "r"(a[0]), "r"(a[1]), "r"(a[2]), "r"(a[3]), "r"(b[0]), "r"(b[1]));
}
__device__ __forceinline__ uint32_t h2pack(float a, float b) {
    __half2 h = __floats2half2_rn(a, b);
    return *(uint32_t*)&h;
}

// ---------------- fp16 mma GEMM ----------------------------------------------
// MODE 0: C = Ah x Bh0^T, fp32 out (O projection; Bh0 already points at Wo^T).
// MODE 1: fused QKV: blockIdx.z picks weight & output; Q/K get RoPE applied
//         in the epilogue (tile cols = one full head), all emitted fp16.
#define NST 3
#define STG_B 32768
#define GEMM_SMEM (NST*STG_B)      // 98304

template<int MODE>
__global__ __launch_bounds__(256, 2) void gemm_h(const __half* __restrict__ Ah,
                                                 const __half* __restrict__ Bh0,
                                                 float* __restrict__ C) {
    extern __shared__ char smem[];
    const int z = MODE ? blockIdx.z : 0;
    const __half* Bh = Bh0 + (size_t)z * CH * CH;
    const uint32_t sb = s2u(smem);
    const int tid  = threadIdx.x;
    const int lane = tid & 31;
    const int wid  = tid >> 5;
    const int wm   = (wid >> 2) * 64;
    const int wn   = (wid & 3) * 32;
    const int row0 = blockIdx.y * 128;
    const int col0 = blockIdx.x * 128;

    float acc[4][4][4];
    #pragma unroll
    for (int i = 0; i < 4; i++)
        #pragma unroll
        for (int j = 0; j < 4; j++)
            #pragma unroll
            for (int r = 0; r < 4; r++) acc[i][j][r] = 0.0f;

    auto load_stage = [&](int slot, int kt) {
        uint32_t ab = sb + slot * STG_B;
        uint32_t bb = ab + 16384;
        #pragma unroll
        for (int i = 0; i < 4; i++) {
            int idx = tid + i * 256;
            int row = idx >> 3, ch = idx & 7;
            uint32_t off = row * 128 + ch * 16;
            uint32_t sw = off ^ ((off >> 3) & 0x70);
            cpa16(ab + sw, Ah + (size_t)(row0 + row) * CH + kt + ch * 8);
            cpa16(bb + sw, Bh + (size_t)(col0 + row) * CH + kt + ch * 8);
        }
    };
    auto compute = [&](int slot) {
        uint32_t ab = sb + slot * STG_B;
        uint32_t bb = ab + 16384;
        #pragma unroll
        for (int ks = 0; ks < 4; ks++) {
            uint32_t aF[4][4], bF[4][2];
            #pragma unroll
            for (int i = 0; i < 4; i++) {
                int row = wm + i * 16 + (lane & 15);
                uint32_t off = row * 128 + ks * 32 + ((lane >> 4) << 4);
                ldm4(aF[i], ab + (off ^ ((off >> 3) & 0x70)));
            }
            #pragma unroll
            for (int j2 = 0; j2 < 2; j2++) {
                int row = wn + j2 * 16 + ((lane >> 4) << 3) + (lane & 7);
                uint32_t off = row * 128 + ks * 32 + (((lane >> 3) & 1) << 4);
                uint32_t r[4];
                ldm4(r, bb + (off ^ ((off >> 3) & 0x70)));
                bF[2 * j2][0] = r[0];  bF[2 * j2][1] = r[1];
                bF[2 * j2 + 1][0] = r[2];  bF[2 * j2 + 1][1] = r[3];
            }
            #pragma unroll
            for (int i = 0; i < 4; i++)
                #pragma unroll
                for (int j = 0; j < 4; j++)
                    mma16(acc[i][j], aF[i], bF[j]);
        }
    };

    load_stage(0, 0);
    asm volatile("cp.async.commit_group;" ::: "memory");
    load_stage(1, 64);
    asm volatile("cp.async.commit_group;" ::: "memory");

    #pragma unroll 1
    for (int it = 0; it < 32; it++) {
        asm volatile("cp.async.wait_group 1;" ::: "memory");
        __syncthreads();
        int jn = it + 2;
        if (jn < 32) load_stage(jn % 3, jn * 64);
        asm volatile("cp.async.commit_group;" ::: "memory");
        compute(it % 3);
    }

    if (MODE == 0) {
        #pragma unroll
        for (int i = 0; i < 4; i++) {
            #pragma unroll
            for (int j = 0; j < 4; j++) {
                int r = row0 + wm + i * 16 + (lane >> 2);
                int c = col0 + wn + j * 8 + 2 * (lane & 3);
                *(float2*)&C[(size_t)r * CH + c] =
                    make_float2(acc[i][j][0], acc[i][j][1]);
                *(float2*)&C[(size_t)(r + 8) * CH + c] =
                    make_float2(acc[i][j][2], acc[i][j][3]);
            }
        }
    } else if (z == 2) {
        // V: direct fp16 store
        #pragma unroll
        for (int i = 0; i < 4; i++) {
            #pragma unroll
            for (int j = 0; j < 4; j++) {
                int r = row0 + wm + i * 16 + (lane >> 2);
                int c = col0 + wn + j * 8 + 2 * (lane & 3);
                uint32_t p0 = h2pack(acc[i][j][0], acc[i][j][1]);
                uint32_t p1 = h2pack(acc[i][j][2], acc[i][j][3]);
                *(uint32_t*)&g_Vh[(size_t)r * CH + c] = p0;
                *(uint32_t*)&g_Vh[(size_t)(r + 8) * CH + c] = p1;
            }
        }
    } else {
        // Q/K: stage to smem, apply RoPE, emit fp16
        const int SP = 132;
        float* st = (float*)smem;
        __syncthreads();
        #pragma unroll
        for (int i = 0; i < 4; i++) {
            #pragma unroll
            for (int j = 0; j < 4; j++) {
                int r1 = wm + i * 16 + (lane >> 2);
                int c  = wn + j * 8 + 2 * (lane & 3);
                *(float2*)&st[r1 * SP + c] =
                    make_float2(acc[i][j][0], acc[i][j][1]);
                *(float2*)&st[(r1 + 8) * SP + c] =
                    make_float2(acc[i][j][2], acc[i][j][3]);
            }
        }
        __syncthreads();
        int r = tid >> 1, hf = tid & 1;
        int t = (row0 + r) & (SEQ - 1);
        __half* Out = (z == 0 ? g_Qh : g_Kh) + (size_t)(row0 + r) * CH + col0;
        int db0 = hf * 32;
        #pragma unroll
        for (int q = 0; q < 8; q++) {
            int db = db0 + q * 4;
            float4 c4 = *(const float4*)&g_cos[(t << 6) + db];
            float4 s4 = *(const float4*)&g_sin[(t << 6) + db];
            float4 u1 = *(const float4*)&st[r * SP + db];
            float4 u2 = *(const float4*)&st[r * SP + db + 64];
            uint2 w1, w2;
            w1.x = h2pack(u1.x * c4.x - u2.x * s4.x, u1.y * c4.y - u2.y * s4.y);
            w1.y = h2pack(u1.z * c4.z - u2.z * s4.z, u1.w * c4.w - u2.w * s4.w);
            w2.x = h2pack(u1.x * s4.x + u2.x * c4.x, u1.y * s4.y + u2.y * c4.y);
            w2.y = h2pack(u1.z * s4.z + u2.z * c4.z, u1.w * s4.w + u2.w * c4.w);
            *(uint2*)&Out[db]      = w1;
            *(uint2*)&Out[db + 64] = w2;
        }
    }
}

// ---------------- prep -------------------------------------------------------
__global__ __launch_bounds__(256) void f32_to_f16(const float4* __restrict__ in,
                                                  __half* __restrict__ out) {
    int i = blockIdx.x * blockDim.x + threadIdx.x;
    float4 v = in[i];
    __half2 h0 = __floats2half2_rn(v.x, v.y);
    __half2 h1 = __floats2half2_rn(v.z, v.w);
    uint2 u = make_uint2(*(uint32_t*)&h0, *(uint32_t*)&h1);
    ((uint2*)out)[i] = u;
}

__global__ __launch_bounds__(256) void transpose4(const float* __restrict__ W0,
                                                  const float* __restrict__ W1,
                                                  const float* __restrict__ W2,
                                                  const float* __restrict__ W3) {
    __shared__ float t[32][33];
    const float* W = (blockIdx.z == 0) ? W0 : (blockIdx.z == 1) ? W1
                   : (blockIdx.z == 2) ? W2 : W3;
    __half* Wt = &g_Wh[blockIdx.z][0];
    int bx = blockIdx.x * 32;
    int by = blockIdx.y * 32;
    int tx = threadIdx.x & 31, ty = threadIdx.x >> 5;
    #pragma unroll
    for (int i = 0; i < 4; i++)
        t[ty + 8 * i][tx] = W[(size_t)(bx + ty + 8 * i) * CH + by + tx];
    __syncthreads();
    int r = threadIdx.x >> 3;
    int c2 = threadIdx.x & 7;
    #pragma unroll
    for (int p = 0; p < 2; p++) {
        int cc = c2 + p * 8;
        __half2 h = __floats2half2_rn(t[2 * cc][r], t[2 * cc + 1][r]);
        ((__half2*)(Wt + (size_t)(by + r) * CH + bx))[cc] = h;
    }
}

// ---------------- RoPE tables ------------------------------------------------
__global__ __launch_bounds__(256) void rope_tab_kernel() {
    int idx = blockIdx.x * blockDim.x + threadIdx.x;
    if (idx >= SEQ * 64) return;
    int d = idx & 63;
    int t = idx >> 6;
    // inv = 10000^(-d/64) = 2^(-d * log2(10000)/64)
    double inv = exp2(-(double)d * 0.20762050593046014);
    double ang = (double)t * inv;
    const double TWO_PI = 6.283185307179586477;
    ang -= floor(ang * (1.0 / TWO_PI)) * TWO_PI;
    float s, c;
    sincosf((float)ang, &s, &c);
    g_cos[idx] = c;
    g_sin[idx] = s;
}

// ---------------- Attention: fp16 mma flash, inverted-window mask -----------
#define ATS 136
#define KV_OFF (64*ATS)
#define STAGE_H (2*64*ATS)
#define ATT_SMEM ((64*ATS + 2*STAGE_H)*2)   // 87040 bytes

__device__ __forceinline__ int next_act(int kb, int q0) {
    do { kb += 64; } while (kb < SEQ && (kb + 63 <= q0) && (kb >= q0 - (WIN - 64)));
    return kb;
}

__global__ __launch_bounds__(128) void attn_mma_kernel() {
    extern __shared__ char smem[];
    const uint32_t sb = s2u(smem);
    const int bh = blockIdx.y;
    const int b = bh >> 4;
    const int h = bh & 15;
    const int q0 = blockIdx.x * 64;
    const int tid = threadIdx.x;
    const int lane = tid & 31;
    const int w = tid >> 5;
    const float scale = 0.08838834764831845f;

    const __half* Qg = g_Qh + ((size_t)(b * SEQ) + q0) * CH + h * HD;

    auto load_kv = [&](int stage, int kb) {
        const __half* Kg = g_Kh + ((size_t)(b * SEQ) + kb) * CH + h * HD;
        const __half* Vg = g_Vh + ((size_t)(b * SEQ) + kb) * CH + h * HD;
        uint32_t kbB = sb + (KV_OFF + stage * STAGE_H) * 2;
        uint32_t vbB = kbB + 64 * ATS * 2;
        #pragma unroll
        for (int i = 0; i < 8; i++) {
            int idx = tid + i * 128;
            int row = idx >> 4, ch = idx & 15;
            uint32_t d = (row * ATS + ch * 8) * 2;
            cpa16(kbB + d, Kg + (size_t)row * CH + ch * 8);
            cpa16(vbB + d, Vg + (size_t)row * CH + ch * 8);
        }
    };

    {
        #pragma unroll
        for (int i = 0; i < 8; i++) {
            int idx = tid + i * 128;
            int row = idx >> 4, ch = idx & 15;
            cpa16(sb + (row * ATS + ch * 8) * 2, Qg + (size_t)row * CH + ch * 8);
        }
    }

    int cur = next_act(-64, q0);
    load_kv(0, cur);
    asm volatile("cp.async.commit_group;" ::: "memory");
    int nxt = next_act(cur, q0);
    if (nxt < SEQ) load_kv(1, nxt);
    asm volatile("cp.async.commit_group;" ::: "memory");
    int nn = (nxt < SEQ) ? next_act(nxt, q0) : SEQ;

    float m0 = -1e30f, m1 = -1e30f, l0 = 0.0f, l1 = 0.0f;
    float oacc[16][4];
    #pragma unroll
    for (int t = 0; t < 16; t++)
        #pragma unroll
        for (int r = 0; r < 4; r++) oacc[t][r] = 0.0f;

    int stage = 0;
    #pragma unroll 1
    while (cur < SEQ) {
        asm volatile("cp.async.wait_group 1;" ::: "memory");
        __syncthreads();

        uint32_t kbB = sb + (KV_OFF + stage * STAGE_H) * 2;
        uint32_t vbB = kbB + 64 * ATS * 2;

        float sacc[8][4];
        #pragma unroll
        for (int t = 0; t < 8; t++)
            #pragma unroll
            for (int r = 0; r < 4; r++) sacc[t][r] = 0.0f;

        #pragma unroll
        for (int ks = 0; ks < 8; ks++) {
            uint32_t aF[4];
            {
                int row = 16 * w + (lane & 15);
                uint32_t off = (row * ATS + ks * 16 + 8 * (lane >> 4)) * 2;
                ldm4(aF, sb + off);
            }
            #pragma unroll
            for (int jp = 0; jp < 4; jp++) {
                int row = 16 * jp + ((lane >> 4) << 3) + (lane & 7);
                uint32_t off = (row * ATS + ks * 16 + 8 * ((lane >> 3) & 1)) * 2;
                uint32_t r[4];
                ldm4(r, kbB + off);
                mma16(sacc[2 * jp],     aF, r);
                mma16(sacc[2 * jp + 1], aF, r + 2);
            }
        }

        int i0 = q0 + 16 * w + (lane >> 2);
        int i1 = i0 + 8;
        #pragma unroll
        for (int t = 0; t < 8; t++) {
            int j0 = cur + 8 * t + 2 * (lane & 3);
            #pragma unroll
            for (int e = 0; e < 2; e++) {
                int j = j0 + e;
                float v0 = sacc[t][e] * scale;
                float v1 = sacc[t][2 + e] * scale;
                bool msk0 = (j <= i0) && (j >= i0 - (WIN - 1));
                bool msk1 = (j <= i1) && (j >= i1 - (WIN - 1));
                sacc[t][e]     = msk0 ? -1e30f : v0;
                sacc[t][2 + e] = msk1 ? -1e30f : v1;
            }
        }

        float rmax0 = -1e30f, rmax1 = -1e30f;
        #pragma unroll
        for (int t = 0; t < 8; t++) {
            rmax0 = fmaxf(rmax0, fmaxf(sacc[t][0], sacc[t][1]));
            rmax1 = fmaxf(rmax1, fmaxf(sacc[t][2], sacc[t][3]));
        }
        rmax0 = fmaxf(rmax0, __shfl_xor_sync(0xffffffffu, rmax0, 1));
        rmax0 = fmaxf(rmax0, __shfl_xor_sync(0xffffffffu, rmax0, 2));
        rmax1 = fmaxf(rmax1, __shfl_xor_sync(0xffffffffu, rmax1, 1));
        rmax1 = fmaxf(rmax1, __shfl_xor_sync(0xffffffffu, rmax1, 2));
        float mn0 = fmaxf(m0, rmax0), mn1 = fmaxf(m1, rmax1);
        float cr0 = __expf(m0 - mn0), cr1 = __expf(m1 - mn1);
        float ps0 = 0.0f, ps1 = 0.0f;
        #pragma unroll
        for (int t = 0; t < 8; t++) {
            sacc[t][0] = __expf(sacc[t][0] - mn0);
            sacc[t][1] = __expf(sacc[t][1] - mn0);
            sacc[t][2] = __expf(sacc[t][2] - mn1);
            sacc[t][3] = __expf(sacc[t][3] - mn1);
            ps0 += sacc[t][0] + sacc[t][1];
            ps1 += sacc[t][2] + sacc[t][3];
        }
        ps0 += __shfl_xor_sync(0xffffffffu, ps0, 1);
        ps0 += __shfl_xor_sync(0xffffffffu, ps0, 2);
        ps1 += __shfl_xor_sync(0xffffffffu, ps1, 1);
        ps1 += __shfl_xor_sync(0xffffffffu, ps1, 2);
        l0 = l0 * cr0 + ps0;  m0 = mn0;
        l1 = l1 * cr1 + ps1;  m1 = mn1;
        #pragma unroll
        for (int t = 0; t < 16; t++) {
            oacc[t][0] *= cr0;  oacc[t][1] *= cr0;
            oacc[t][2] *= cr1;  oacc[t][3] *= cr1;
        }

        uint32_t aP[4][4];
        #pragma unroll
        for (int k2 = 0; k2 < 4; k2++) {
            aP[k2][0] = h2pack(sacc[2 * k2][0],     sacc[2 * k2][1]);
            aP[k2][1] = h2pack(sacc[2 * k2][2],     sacc[2 * k2][3]);
            aP[k2][2] = h2pack(sacc[2 * k2 + 1][0], sacc[2 * k2 + 1][1]);
            aP[k2][3] = h2pack(sacc[2 * k2 + 1][2], sacc[2 * k2 + 1][3]);
        }

        #pragma unroll
        for (int k2 = 0; k2 < 4; k2++) {
            #pragma unroll
            for (int dt = 0; dt < 8; dt++) {
                int row = 16 * k2 + ((lane >> 3) & 1) * 8 + (lane & 7);
                uint32_t off = (row * ATS + dt * 16 + ((lane >> 4) << 3)) * 2;
                uint32_t r[4];
                ldm4t(r, vbB + off);
                mma16(oacc[2 * dt],     aP[k2], r);
                mma16(oacc[2 * dt + 1], aP[k2], r + 2);
            }
        }

        __syncthreads();
        if (nn < SEQ) load_kv(stage, nn);
        asm volatile("cp.async.commit_group;" ::: "memory");
        cur = nxt;  nxt = nn;
        nn = (nn < SEQ) ? next_act(nn, q0) : SEQ;
        stage ^= 1;
    }

    float il0 = 1.0f / l0, il1 = 1.0f / l1;
    int r0 = q0 + 16 * w + (lane >> 2);
    __half* Og = g_Ah + (size_t)(b * SEQ) * CH + h * HD;
    #pragma unroll
    for (int t = 0; t < 16; t++) {
        int c = 8 * t + 2 * (lane & 3);
        __half2 h0 = __floats2half2_rn(oacc[t][0] * il0, oacc[t][1] * il0);
        __half2 h1 = __floats2half2_rn(oacc[t][2] * il1, oacc[t][3] * il1);
        *(__half2*)&Og[(size_t)r0 * CH + c] = h0;
        *(__half2*)&Og[(size_t)(r0 + 8) * CH + c] = h1;
    }
}

// ---------------- launch ----------------------------------------------------
extern "C" void kernel_launch(void* const* d_in, const int* in_sizes, int n_in,
                              void* d_out, int out_size) {
    const float* x  = (const float*)d_in[0];
    const float* Wq = (const float*)d_in[1];
    const float* Wk = (const float*)d_in[2];
    const float* Wv = (const float*)d_in[3];
    const float* Wo = (const float*)d_in[4];
    float* out = (float*)d_out;

    __half *Xh, *Wh, *Ahp;
    cudaGetSymbolAddress((void**)&Xh, g_Xh);
    cudaGetSymbolAddress((void**)&Wh, g_Wh);
    cudaGetSymbolAddress((void**)&Ahp, g_Ah);
    __half* Wh3 = Wh + 3 * (size_t)CH * CH;

    static bool attr_set = false;
    if (!attr_set) {
        cudaFuncSetAttribute(gemm_h<0>,
                             cudaFuncAttributeMaxDynamicSharedMemorySize,
                             GEMM_SMEM);
        cudaFuncSetAttribute(gemm_h<1>,
                             cudaFuncAttributeMaxDynamicSharedMemorySize,
                             GEMM_SMEM);
        cudaFuncSetAttribute(attn_mma_kernel,
                             cudaFuncAttributeMaxDynamicSharedMemorySize,
                             ATT_SMEM);
        attr_set = true;
    }

    f32_to_f16<<<(MROWS * CH / 4) / 256, 256>>>((const float4*)x, Xh);
    transpose4<<<dim3(CH / 32, CH / 32, 4), 256>>>(Wq, Wk, Wv, Wo);
    rope_tab_kernel<<<(SEQ * 64) / 256, 256>>>();

    dim3 gq(CH / 128, MROWS / 128, 3);
    gemm_h<1><<<gq, 256, GEMM_SMEM>>>(Xh, Wh, nullptr);

    attn_mma_kernel<<<dim3(SEQ / 64, BATCH * NH), 128, ATT_SMEM>>>();

    dim3 gg(CH / 128, MROWS / 128, 1);
    gemm_h<0><<<gg, 256, GEMM_SMEM>>>(Ahp, Wh3, out);
}